// round 11
// baseline (speedup 1.0000x reference)
#include <cuda_runtime.h>
#include <cuda_fp16.h>

// WordHashing: sparse [B=16384 x 30000] (COO, rows sorted) @ W [30000 x 300] + bias, ReLU.
// R10 post-mortem: spmm stable at ~30us, issue 54%, occ 50% — latency-bound; rows
// average ONE 32-nnz chunk so each warp has ~160cyc of issue work vs ~1000cyc of
// serial L2 latency. R11: TWO rows per warp (dual accumulator sets, joint inner
// loop, unroll 4 x 2 rows = 8 LDGs in flight) to double per-warp issue work
// against the same latency chain.

#define OUT_DIM   300
#define IN_DIM    30000
#define ROW_INT4  38           // 38 x 16B = 608B per padded fp16 row (304 halves)
#define ROW_BYTES 608
#define MAX_BATCH 16384

#define CONV_THREADS 256
#define CONV_BLOCKS  ((IN_DIM * ROW_INT4 + CONV_THREADS - 1) / CONV_THREADS)

__device__ int g_row_start[MAX_BATCH + 1];
__device__ __align__(128) int4 g_Wh4[IN_DIM * ROW_INT4];   // 18.2 MB fp16 staged weights

// ---------------------------------------------------------------------------
// Fused prep: blocks [0, CONV_BLOCKS) convert W f32 -> padded f16 rows;
// remaining blocks build row_start from sorted sp_rows.
__global__ void prep_kernel(const float* __restrict__ W,
                            const int* __restrict__ rows,
                            int nnz, int batch, int conv_blocks_thr) {
    if (blockIdx.x < (unsigned)conv_blocks_thr) {
        const int i = blockIdx.x * CONV_THREADS + threadIdx.x;
        if (i >= IN_DIM * ROW_INT4) return;
        const int row = i / ROW_INT4;
        const int k   = i - row * ROW_INT4;
        const int col = k * 8;

        float4 a = make_float4(0.f, 0.f, 0.f, 0.f);
        float4 b = make_float4(0.f, 0.f, 0.f, 0.f);
        const float4* src = reinterpret_cast<const float4*>(W + (size_t)row * OUT_DIM + col);
        if (col + 8 <= OUT_DIM)      { a = __ldg(src); b = __ldg(src + 1); }
        else if (col < OUT_DIM)      { a = __ldg(src); }   // k==37: cols 296..299

        __align__(16) __half2 hh[4];
        hh[0] = __floats2half2_rn(a.x, a.y);
        hh[1] = __floats2half2_rn(a.z, a.w);
        hh[2] = __floats2half2_rn(b.x, b.y);
        hh[3] = __floats2half2_rn(b.z, b.w);
        g_Wh4[i] = *reinterpret_cast<const int4*>(hh);
    } else {
        const int i = (blockIdx.x - conv_blocks_thr) * CONV_THREADS + threadIdx.x;
        if (i >= nnz) return;
        int r  = rows[i];
        int rp = (i == 0) ? -1 : rows[i - 1];
        for (int q = rp + 1; q <= r; ++q) g_row_start[q] = i;
        if (i == nnz - 1) {
            for (int q = r + 1; q <= batch; ++q) g_row_start[q] = nnz;
        }
    }
}

// ---------------------------------------------------------------------------
// Packed convert+FMA: acc(f32x2) += cvt(f16x2 w2) * vv(f32x2).
__device__ __forceinline__ void cvt_fma2(unsigned long long& acc,
                                         unsigned int w2,
                                         unsigned long long vv) {
    __half2 h;
    *reinterpret_cast<unsigned int*>(&h) = w2;
    const float2 wf = __half22float2(h);            // 2x F2F, selector form
    asm("{\n\t"
        ".reg .b64 wp;\n\t"
        "mov.b64 wp, {%1, %2};\n\t"
        "fma.rn.f32x2 %0, wp, %3, %0;\n\t"
        "}" : "+l"(acc) : "f"(wf.x), "f"(wf.y), "l"(vv));
}

// One nnz: gather this lane's 8+2 cols of weight row (offset pre-multiplied) and
// accumulate into the given f32x2 accumulator set.
__device__ __forceinline__ void process_nnz(const int2 cv,
                                            const char* __restrict__ lbase,
                                            int tail_imm, bool has_tail,
                                            unsigned long long* acc) {
    const float v = __int_as_float(cv.y);
    unsigned long long vv;
    asm("mov.b64 %0, {%1, %1};" : "=l"(vv) : "f"(v));
    const char* p = lbase + cv.x;
    const int4 w4 = __ldg(reinterpret_cast<const int4*>(p));
    int w1 = 0;
    if (has_tail) w1 = __ldg(reinterpret_cast<const int*>(p + tail_imm));
    cvt_fma2(acc[0], (unsigned)w4.x, vv);
    cvt_fma2(acc[1], (unsigned)w4.y, vv);
    cvt_fma2(acc[2], (unsigned)w4.z, vv);
    cvt_fma2(acc[3], (unsigned)w4.w, vv);
    cvt_fma2(acc[4], (unsigned)w1,   vv);
}

__device__ __forceinline__ void epilogue_row(const unsigned long long* a,
                                             const float* __restrict__ bias,
                                             float* __restrict__ out,
                                             int row, int lane) {
    float acc[10];
    asm("mov.b64 {%0, %1}, %2;" : "=f"(acc[0]), "=f"(acc[1]) : "l"(a[0]));
    asm("mov.b64 {%0, %1}, %2;" : "=f"(acc[2]), "=f"(acc[3]) : "l"(a[1]));
    asm("mov.b64 {%0, %1}, %2;" : "=f"(acc[4]), "=f"(acc[5]) : "l"(a[2]));
    asm("mov.b64 {%0, %1}, %2;" : "=f"(acc[6]), "=f"(acc[7]) : "l"(a[3]));
    asm("mov.b64 {%0, %1}, %2;" : "=f"(acc[8]), "=f"(acc[9]) : "l"(a[4]));

    float* orow = out + (size_t)row * OUT_DIM;
    const int c0 = lane * 8;                   // 0..248
    const float4 b0 = __ldg(reinterpret_cast<const float4*>(bias + c0));
    const float4 b1 = __ldg(reinterpret_cast<const float4*>(bias + c0 + 4));
    float4 o0, o1;
    o0.x = fmaxf(acc[0] + b0.x, 0.f);  o0.y = fmaxf(acc[1] + b0.y, 0.f);
    o0.z = fmaxf(acc[2] + b0.z, 0.f);  o0.w = fmaxf(acc[3] + b0.w, 0.f);
    o1.x = fmaxf(acc[4] + b1.x, 0.f);  o1.y = fmaxf(acc[5] + b1.y, 0.f);
    o1.z = fmaxf(acc[6] + b1.z, 0.f);  o1.w = fmaxf(acc[7] + b1.w, 0.f);
    *reinterpret_cast<float4*>(orow + c0)     = o0;
    *reinterpret_cast<float4*>(orow + c0 + 4) = o1;

    const int c1 = 256 + 2 * lane;             // tail cols; valid while < 300
    if (c1 < OUT_DIM) {                        // lanes 0..21
        const float2 b2 = __ldg(reinterpret_cast<const float2*>(bias + c1));
        float2 o2;
        o2.x = fmaxf(acc[8] + b2.x, 0.f);
        o2.y = fmaxf(acc[9] + b2.y, 0.f);
        *reinterpret_cast<float2*>(orow + c1) = o2;
    }
}

// ---------------------------------------------------------------------------
// spmm: 128-thread CTA = 4 warps; each warp owns TWO adjacent sparse rows.
// Joint inner loop keeps 8 independent LDG.128s in flight per warp.
__global__ __launch_bounds__(128) void spmm_row_kernel(
    const int*   __restrict__ cols,
    const float* __restrict__ vals,
    const float* __restrict__ bias,
    float*       __restrict__ out,
    int batch)
{
    __shared__ int2 s_cv[4][2][32];
    const int warp = threadIdx.x >> 5;
    const int lane = threadIdx.x & 31;
    const int row0 = (blockIdx.x * 4 + warp) * 2;
    const int row1 = row0 + 1;
    if (row0 >= batch) return;

    const int s0 = g_row_start[row0];
    const int e0 = g_row_start[row0 + 1];
    int s1 = 0, e1 = 0;
    if (row1 < batch) { s1 = g_row_start[row1]; e1 = g_row_start[row1 + 1]; }

    unsigned long long A[5] = {0ull, 0ull, 0ull, 0ull, 0ull};
    unsigned long long B[5] = {0ull, 0ull, 0ull, 0ull, 0ull};

    const char* __restrict__ lbase =
        reinterpret_cast<const char*>(g_Wh4) + lane * 16;
    const int tail_imm = 512 - lane * 16 + lane * 4;   // rowp+512+4*lane rel. to lbase
    const bool has_tail = (lane < 22);

    for (int b0 = s0, b1 = s1; b0 < e0 || b1 < e1; b0 += 32, b1 += 32) {
        int n0 = e0 - b0;  n0 = n0 < 0 ? 0 : (n0 > 32 ? 32 : n0);
        int n1 = e1 - b1;  n1 = n1 < 0 ? 0 : (n1 > 32 ? 32 : n1);
        if (lane < n0)
            s_cv[warp][0][lane] = make_int2(__ldg(cols + b0 + lane) * ROW_BYTES,
                                            __float_as_int(__ldg(vals + b0 + lane)));
        if (lane < n1)
            s_cv[warp][1][lane] = make_int2(__ldg(cols + b1 + lane) * ROW_BYTES,
                                            __float_as_int(__ldg(vals + b1 + lane)));
        __syncwarp();

        const int jm = n0 < n1 ? n0 : n1;
        #pragma unroll 4
        for (int j = 0; j < jm; ++j) {          // joint section: 2 indep streams
            process_nnz(s_cv[warp][0][j], lbase, tail_imm, has_tail, A);
            process_nnz(s_cv[warp][1][j], lbase, tail_imm, has_tail, B);
        }
        #pragma unroll 4
        for (int j = jm; j < n0; ++j)
            process_nnz(s_cv[warp][0][j], lbase, tail_imm, has_tail, A);
        #pragma unroll 4
        for (int j = jm; j < n1; ++j)
            process_nnz(s_cv[warp][1][j], lbase, tail_imm, has_tail, B);
        __syncwarp();                            // before restaging smem
    }

    epilogue_row(A, bias, out, row0, lane);
    if (row1 < batch) epilogue_row(B, bias, out, row1, lane);
}

extern "C" void kernel_launch(void* const* d_in, const int* in_sizes, int n_in,
                              void* d_out, int out_size) {
    const int*   sp_rows = (const int*)  d_in[0];
    const int*   sp_cols = (const int*)  d_in[1];
    const float* sp_vals = (const float*)d_in[2];
    const float* weights = (const float*)d_in[3];
    const float* bias    = (const float*)d_in[4];

    const int nnz   = in_sizes[0];
    const int batch = out_size / OUT_DIM;

    const int build_blocks = (nnz + CONV_THREADS - 1) / CONV_THREADS;
    prep_kernel<<<CONV_BLOCKS + build_blocks, CONV_THREADS>>>(
        weights, sp_rows, nnz, batch, CONV_BLOCKS);
    const int rows_per_cta = 8;                 // 4 warps x 2 rows
    spmm_row_kernel<<<(batch + rows_per_cta - 1) / rows_per_cta, 128>>>(
        sp_cols, sp_vals, bias, (float*)d_out, batch);
}

// round 12
// speedup vs baseline: 1.0580x; 1.0580x over previous
#include <cuda_runtime.h>
#include <cuda_fp16.h>

// WordHashing: sparse [B=16384 x 30000] (COO, rows sorted) @ W [30000 x 300] + bias, ReLU.
// R11 post-mortem: 2-rows/warp bought ILP with regs (64) and lost more TLP
// (occ 39%) — reverted. R12 = R10 (best per-warp stream: unroll 8, 46 regs,
// 1 row/warp) with 64-thread CTAs: halves the CTA straggler coupling
// (max-of-2 vs max-of-4 row lengths) and packs residency at finer granularity
// to close the achieved-vs-theoretical occupancy gap (50.4% vs ~65%).

#define OUT_DIM   300
#define IN_DIM    30000
#define ROW_INT4  38           // 38 x 16B = 608B per padded fp16 row (304 halves)
#define ROW_BYTES 608
#define MAX_BATCH 16384

#define CONV_THREADS 256
#define CONV_BLOCKS  ((IN_DIM * ROW_INT4 + CONV_THREADS - 1) / CONV_THREADS)

__device__ int g_row_start[MAX_BATCH + 1];
__device__ __align__(128) int4 g_Wh4[IN_DIM * ROW_INT4];   // 18.2 MB fp16 staged weights

// ---------------------------------------------------------------------------
// Fused prep: blocks [0, CONV_BLOCKS) convert W f32 -> padded f16 rows;
// remaining blocks build row_start from sorted sp_rows.
__global__ void prep_kernel(const float* __restrict__ W,
                            const int* __restrict__ rows,
                            int nnz, int batch, int conv_blocks_thr) {
    if (blockIdx.x < (unsigned)conv_blocks_thr) {
        const int i = blockIdx.x * CONV_THREADS + threadIdx.x;
        if (i >= IN_DIM * ROW_INT4) return;
        const int row = i / ROW_INT4;
        const int k   = i - row * ROW_INT4;
        const int col = k * 8;

        float4 a = make_float4(0.f, 0.f, 0.f, 0.f);
        float4 b = make_float4(0.f, 0.f, 0.f, 0.f);
        const float4* src = reinterpret_cast<const float4*>(W + (size_t)row * OUT_DIM + col);
        if (col + 8 <= OUT_DIM)      { a = __ldg(src); b = __ldg(src + 1); }
        else if (col < OUT_DIM)      { a = __ldg(src); }   // k==37: cols 296..299

        __align__(16) __half2 hh[4];
        hh[0] = __floats2half2_rn(a.x, a.y);
        hh[1] = __floats2half2_rn(a.z, a.w);
        hh[2] = __floats2half2_rn(b.x, b.y);
        hh[3] = __floats2half2_rn(b.z, b.w);
        g_Wh4[i] = *reinterpret_cast<const int4*>(hh);
    } else {
        const int i = (blockIdx.x - conv_blocks_thr) * CONV_THREADS + threadIdx.x;
        if (i >= nnz) return;
        int r  = rows[i];
        int rp = (i == 0) ? -1 : rows[i - 1];
        for (int q = rp + 1; q <= r; ++q) g_row_start[q] = i;
        if (i == nnz - 1) {
            for (int q = r + 1; q <= batch; ++q) g_row_start[q] = nnz;
        }
    }
}

// ---------------------------------------------------------------------------
// Packed convert+FMA: acc(f32x2) += cvt(f16x2 w2) * vv(f32x2).
__device__ __forceinline__ void cvt_fma2(unsigned long long& acc,
                                         unsigned int w2,
                                         unsigned long long vv) {
    __half2 h;
    *reinterpret_cast<unsigned int*>(&h) = w2;
    const float2 wf = __half22float2(h);            // 2x F2F, selector form
    asm("{\n\t"
        ".reg .b64 wp;\n\t"
        "mov.b64 wp, {%1, %2};\n\t"
        "fma.rn.f32x2 %0, wp, %3, %0;\n\t"
        "}" : "+l"(acc) : "f"(wf.x), "f"(wf.y), "l"(vv));
}

// ---------------------------------------------------------------------------
// spmm: 64-thread CTA = 2 warps, one sparse row each.
// Lane t owns cols [8t,8t+8) (LDG.128); lanes 0..21 also own cols [256+2t,+2).
// (col,val) chunks staged via smem int2 {c*608, val}, register-prefetched.
__global__ __launch_bounds__(64) void spmm_row_kernel(
    const int*   __restrict__ cols,
    const float* __restrict__ vals,
    const float* __restrict__ bias,
    float*       __restrict__ out,
    int batch)
{
    __shared__ int2 s_cv[2][2][32];
    const int warp = threadIdx.x >> 5;
    const int lane = threadIdx.x & 31;
    const int row  = blockIdx.x * 2 + warp;
    if (row >= batch) return;

    const int start = g_row_start[row];        // uniform -> broadcast LDG
    const int end   = g_row_start[row + 1];

    unsigned long long a0 = 0ull, a1 = 0ull, a2 = 0ull, a3 = 0ull, a4 = 0ull;

    const char* __restrict__ lbase =
        reinterpret_cast<const char*>(g_Wh4) + lane * 16;
    const int tail_imm = 512 - lane * 16 + lane * 4;   // rowp+512+4*lane rel. to lbase
    const bool has_tail = (lane < 22);

    // Prefetch chunk 0.
    int2 pf = make_int2(0, 0);
    if (start + lane < end) {
        pf = make_int2(__ldg(cols + start + lane) * ROW_BYTES,
                       __float_as_int(__ldg(vals + start + lane)));
    }

    int parity = 0;
    for (int base = start; base < end; base += 32, parity ^= 1) {
        const int rem = end - base;
        const int n   = rem < 32 ? rem : 32;
        s_cv[warp][parity][lane] = pf;         // publish current chunk
        __syncwarp();
        const int nb = base + 32;
        if (nb + lane < end) {                 // prefetch next chunk
            pf = make_int2(__ldg(cols + nb + lane) * ROW_BYTES,
                           __float_as_int(__ldg(vals + nb + lane)));
        }
        #pragma unroll 8
        for (int j = 0; j < n; ++j) {
            const int2  cv = s_cv[warp][parity][j];    // LDS.64 broadcast
            const float v  = __int_as_float(cv.y);
            unsigned long long vv;
            asm("mov.b64 %0, {%1, %1};" : "=l"(vv) : "f"(v));
            const char* p = lbase + cv.x;
            const int4 w4 = __ldg(reinterpret_cast<const int4*>(p));
            int w1 = 0;
            if (has_tail) w1 = __ldg(reinterpret_cast<const int*>(p + tail_imm));
            cvt_fma2(a0, (unsigned)w4.x, vv);
            cvt_fma2(a1, (unsigned)w4.y, vv);
            cvt_fma2(a2, (unsigned)w4.z, vv);
            cvt_fma2(a3, (unsigned)w4.w, vv);
            cvt_fma2(a4, (unsigned)w1,   vv);
        }
    }

    float acc[10];
    asm("mov.b64 {%0, %1}, %2;" : "=f"(acc[0]), "=f"(acc[1]) : "l"(a0));
    asm("mov.b64 {%0, %1}, %2;" : "=f"(acc[2]), "=f"(acc[3]) : "l"(a1));
    asm("mov.b64 {%0, %1}, %2;" : "=f"(acc[4]), "=f"(acc[5]) : "l"(a2));
    asm("mov.b64 {%0, %1}, %2;" : "=f"(acc[6]), "=f"(acc[7]) : "l"(a3));
    asm("mov.b64 {%0, %1}, %2;" : "=f"(acc[8]), "=f"(acc[9]) : "l"(a4));

    // Epilogue: +bias, ReLU, coalesced stores.
    float* orow = out + (size_t)row * OUT_DIM;
    const int c0 = lane * 8;                   // 0..248
    const float4 b0 = __ldg(reinterpret_cast<const float4*>(bias + c0));
    const float4 b1 = __ldg(reinterpret_cast<const float4*>(bias + c0 + 4));
    float4 o0, o1;
    o0.x = fmaxf(acc[0] + b0.x, 0.f);  o0.y = fmaxf(acc[1] + b0.y, 0.f);
    o0.z = fmaxf(acc[2] + b0.z, 0.f);  o0.w = fmaxf(acc[3] + b0.w, 0.f);
    o1.x = fmaxf(acc[4] + b1.x, 0.f);  o1.y = fmaxf(acc[5] + b1.y, 0.f);
    o1.z = fmaxf(acc[6] + b1.z, 0.f);  o1.w = fmaxf(acc[7] + b1.w, 0.f);
    *reinterpret_cast<float4*>(orow + c0)     = o0;
    *reinterpret_cast<float4*>(orow + c0 + 4) = o1;

    const int c1 = 256 + 2 * lane;             // tail cols; valid while < 300
    if (c1 < OUT_DIM) {                        // lanes 0..21
        const float2 b2 = __ldg(reinterpret_cast<const float2*>(bias + c1));
        float2 o2;
        o2.x = fmaxf(acc[8] + b2.x, 0.f);
        o2.y = fmaxf(acc[9] + b2.y, 0.f);
        *reinterpret_cast<float2*>(orow + c1) = o2;
    }
}

extern "C" void kernel_launch(void* const* d_in, const int* in_sizes, int n_in,
                              void* d_out, int out_size) {
    const int*   sp_rows = (const int*)  d_in[0];
    const int*   sp_cols = (const int*)  d_in[1];
    const float* sp_vals = (const float*)d_in[2];
    const float* weights = (const float*)d_in[3];
    const float* bias    = (const float*)d_in[4];

    const int nnz   = in_sizes[0];
    const int batch = out_size / OUT_DIM;

    const int build_blocks = (nnz + CONV_THREADS - 1) / CONV_THREADS;
    prep_kernel<<<CONV_BLOCKS + build_blocks, CONV_THREADS>>>(
        weights, sp_rows, nnz, batch, CONV_BLOCKS);
    spmm_row_kernel<<<(batch + 1) / 2, 64>>>(sp_cols, sp_vals, bias,
                                             (float*)d_out, batch);
}